// round 8
// baseline (speedup 1.0000x reference)
#include <cuda_runtime.h>
#include <cuda_bf16.h>
#include <cstdint>

#define D   512
#define SEQ 1024
#define BB  4
#define NH  8
#define NL  6
#define FFD 2048
#define VOC 512
#define TOK (BB*SEQ)   // 4096
#define DD  (D*D)

// weight scratch offsets (element counts into g_wh/g_wl)
#define OFF_QKV 0                          // per layer: [wq; wk; wv] = 3*DD
#define OFF_WO  (18*DD)
#define OFF_W1  (24*DD)
#define OFF_W2  (OFF_W1 + 6*FFD*D)
#define OFF_LM  (OFF_W2 + 6*D*FFD)
#define W_TOTAL (OFF_LM + VOC*D)

// ---------------- device scratch (no allocations allowed) ----------------
__device__ float g_x[TOK*D];               // residual stream (fp32)
__device__ float g_t[TOK*D];               // gemm temp (fp32)
__device__ float g_bcat[NL*3*D];           // concat qkv bias
__device__ __nv_bfloat16 g_xh[TOK*D],  g_xl[TOK*D];    // residual hi/lo
__device__ __nv_bfloat16 g_qh[TOK*D],  g_ql[TOK*D];    // Q hi/lo
__device__ __nv_bfloat16 g_kh[TOK*D],  g_kl[TOK*D];    // K hi/lo
__device__ __nv_bfloat16 g_vh[TOK*D],  g_vl[TOK*D];    // V hi/lo
__device__ __nv_bfloat16 g_oh[TOK*D],  g_ol[TOK*D];    // attn out hi/lo
__device__ __nv_bfloat16 g_fh[TOK*FFD], g_fl[TOK*FFD]; // ffn hidden hi/lo
__device__ __nv_bfloat16 g_wh[W_TOTAL], g_wl[W_TOTAL]; // weights hi/lo
__device__ int g_idmode;

// ---------------- helpers ----------------
__device__ __forceinline__ uint32_t smem_u32(const void* p) {
    uint32_t a;
    asm("{ .reg .u64 t; cvta.to.shared.u64 t, %1; cvt.u32.u64 %0, t; }"
        : "=r"(a) : "l"(p));
    return a;
}
__device__ __forceinline__ void ldsm4(uint32_t* r, uint32_t addr) {
    asm volatile("ldmatrix.sync.aligned.m8n8.x4.shared.b16 {%0,%1,%2,%3}, [%4];"
                 : "=r"(r[0]), "=r"(r[1]), "=r"(r[2]), "=r"(r[3]) : "r"(addr));
}
__device__ __forceinline__ void ldsm4t(uint32_t* r, uint32_t addr) {
    asm volatile("ldmatrix.sync.aligned.m8n8.x4.trans.shared.b16 {%0,%1,%2,%3}, [%4];"
                 : "=r"(r[0]), "=r"(r[1]), "=r"(r[2]), "=r"(r[3]) : "r"(addr));
}
__device__ __forceinline__ void mma_bf16(float* d, const uint32_t* a,
                                         const uint32_t* b) {
    asm volatile("mma.sync.aligned.m16n8k16.row.col.f32.bf16.bf16.f32 "
                 "{%0,%1,%2,%3}, {%4,%5,%6,%7}, {%8,%9}, {%0,%1,%2,%3};"
                 : "+f"(d[0]), "+f"(d[1]), "+f"(d[2]), "+f"(d[3])
                 : "r"(a[0]), "r"(a[1]), "r"(a[2]), "r"(a[3]),
                   "r"(b[0]), "r"(b[1]));
}
#define CPA(dst, src) \
    asm volatile("cp.async.ca.shared.global [%0], [%1], 16;" :: "r"(dst), "l"(src))
#define CPC()  asm volatile("cp.async.commit_group;" ::: "memory")
#define CPW1() asm volatile("cp.async.wait_group 1;" ::: "memory")
#define CPW0() asm volatile("cp.async.wait_group 0;" ::: "memory")

__device__ __forceinline__ uint32_t pack_hi(float a, float b) {
    return (uint32_t)__bfloat16_as_ushort(__float2bfloat16(a)) |
           ((uint32_t)__bfloat16_as_ushort(__float2bfloat16(b)) << 16);
}
__device__ __forceinline__ uint32_t pack_lo(float a, float b) {
    float ra = a - __bfloat162float(__float2bfloat16(a));
    float rb = b - __bfloat162float(__float2bfloat16(b));
    return (uint32_t)__bfloat16_as_ushort(__float2bfloat16(ra)) |
           ((uint32_t)__bfloat16_as_ushort(__float2bfloat16(rb)) << 16);
}
// fast exp: 2^(x*log2e) via 5-FMA poly + exponent bit-stuff (no MUFU)
__device__ __forceinline__ float fexp(float x) {
    x = fmaxf(x, -80.0f);
    float t = x * 1.4426950408889634f;
    float fi = rintf(t);
    float f = t - fi;
    float p =              1.3333558146e-3f;
    p = fmaf(p, f, 9.6180209764e-3f);
    p = fmaf(p, f, 5.5504108664e-2f);
    p = fmaf(p, f, 2.4022650695e-1f);
    p = fmaf(p, f, 6.9314718056e-1f);
    p = fmaf(p, f, 1.0f);
    return __int_as_float(((int)fi + 127) << 23) * p;
}

// ------- weight conversion: fp32 -> bf16 hi/lo, with per-layer restride ----
// dst index = (i/npl)*stride + off + (i%npl). For plain copy pass npl=n, stride=0, off=0.
__global__ void conv_w(const float* __restrict__ src,
                       __nv_bfloat16* __restrict__ hi,
                       __nv_bfloat16* __restrict__ lo,
                       int n, int npl, long stride, long off)
{
    int i = (blockIdx.x * 256 + threadIdx.x) * 4;
    if (i >= n) return;
    int l = i / npl, r = i - l * npl;
    size_t d = (size_t)l * stride + off + r;
    float4 v = *(const float4*)(src + i);
    *(uint32_t*)&hi[d]     = pack_hi(v.x, v.y);
    *(uint32_t*)&hi[d + 2] = pack_hi(v.z, v.w);
    *(uint32_t*)&lo[d]     = pack_lo(v.x, v.y);
    *(uint32_t*)&lo[d + 2] = pack_lo(v.z, v.w);
}

// concat qkv biases into g_bcat[l][1536]
__global__ void bcat_kernel(const float* __restrict__ bq,
                            const float* __restrict__ bk,
                            const float* __restrict__ bv)
{
    int i = blockIdx.x * 256 + threadIdx.x;
    if (i >= NL * 3 * D) return;
    int l = i / (3 * D), r = i % (3 * D);
    int part = r >> 9, d = r & 511;
    const float* s = part == 0 ? bq : part == 1 ? bk : bv;
    g_bcat[i] = s[l * D + d];
}

// ---------------- input_ids dtype detection ----------------
__global__ void detect_ids_kernel(const int* __restrict__ p) {
    __shared__ int any;
    if (threadIdx.x == 0) any = 0;
    __syncthreads();
    int loc = 0;
    for (int i = threadIdx.x; i < 2048; i += blockDim.x) loc |= p[2*i + 1];
    if (loc) atomicOr(&any, 1);
    __syncthreads();
    if (threadIdx.x == 0) g_idmode = any ? 1 : 0;
}

// ---------------- embedding + positional encoding (fp32 + hi/lo) -------
__global__ void embed_kernel(const int* __restrict__ ids,
                             const float* __restrict__ emb) {
    int bs = blockIdx.x;
    int s  = bs & (SEQ - 1);
    int id = g_idmode ? ids[bs] : ids[2*bs];
    const float* e = emb + (size_t)id * D;
    const float c = -9.210340371976184f / 512.0f;
    const int d0 = threadIdx.x * 4;
    float v[4];
    #pragma unroll
    for (int j = 0; j < 4; j++) {
        int d = d0 + j;
        float ang = (float)s * expf(c * (float)(d & ~1));
        float pe  = (d & 1) ? cosf(ang) : sinf(ang);
        v[j] = e[d] * 22.627416997969522f + pe;
    }
    const size_t off = (size_t)bs * D + d0;
    *(float4*)&g_x[off] = make_float4(v[0], v[1], v[2], v[3]);
    *(uint32_t*)&g_xh[off]     = pack_hi(v[0], v[1]);
    *(uint32_t*)&g_xh[off + 2] = pack_hi(v[2], v[3]);
    *(uint32_t*)&g_xl[off]     = pack_lo(v[0], v[1]);
    *(uint32_t*)&g_xl[off + 2] = pack_lo(v[2], v[3]);
}

// =====================================================================
// bf16 tensor-core GEMM, multi-stage cp.async pipeline (1 sync/chunk).
// C = A @ W^T (+bias, opt ReLU). 3-term hi/lo split, fp32 acc.
// BN=64: 3 stages; BN=128: 2 stages. QKV mode: KH!=null -> N=1536 input,
// per-CTA output select into (Ch,Cl)/(KH,KL)/(VH,VL), store stride 512.
// =====================================================================
template<int BN>
__device__ __forceinline__ void load_chunk(
    uint32_t sbuf,
    const __nv_bfloat16* __restrict__ Ah, const __nv_bfloat16* __restrict__ Al,
    const __nv_bfloat16* __restrict__ Wh, const __nv_bfloat16* __restrict__ Wl,
    int m0, int n0, int K, int kc, int tid)
{
    #pragma unroll
    for (int t = 0; t < 4; t++) {
        int s = tid + t * 256;
        int reg = s >> 9;
        int row = (s >> 2) & 127;
        int seg = s & 3;
        uint32_t dst = sbuf + reg * 10240 + row * 80 + seg * 16;
        const __nv_bfloat16* src = (reg ? Al : Ah) + (size_t)(m0 + row) * K + kc + seg * 8;
        CPA(dst, src);
    }
    #pragma unroll
    for (int t = 0; t < BN / 32; t++) {
        int s = tid + t * 256;
        int reg = s / (BN * 4);
        int row = (s >> 2) & (BN - 1);
        int seg = s & 3;
        uint32_t dst = sbuf + 20480 + reg * (BN * 80) + row * 80 + seg * 16;
        const __nv_bfloat16* src = (reg ? Wl : Wh) + (size_t)(n0 + row) * K + kc + seg * 8;
        CPA(dst, src);
    }
}

template<int BN>
__global__ void __launch_bounds__(256, 2) gemm_bf(
    const __nv_bfloat16* __restrict__ Ah, const __nv_bfloat16* __restrict__ Al,
    const __nv_bfloat16* __restrict__ Wh, const __nv_bfloat16* __restrict__ Wl,
    const float* __restrict__ bias, float* __restrict__ C,
    __nv_bfloat16* __restrict__ Ch, __nv_bfloat16* __restrict__ Cl,
    __nv_bfloat16* __restrict__ KH, __nv_bfloat16* __restrict__ KL,
    __nv_bfloat16* __restrict__ VH, __nv_bfloat16* __restrict__ VL,
    int M, int N, int K, int relu)
{
    extern __shared__ char sm[];
    const uint32_t smb = smem_u32(sm);
    constexpr int BUFSZ = 20480 + 2 * BN * 80;
    constexpr int ST = (BN == 64) ? 3 : 2;
    constexpr int MT = (BN == 64) ? 2 : 4;
    const int tid = threadIdx.x, wid = tid >> 5, lane = tid & 31;
    const int wm = (BN == 64) ? (wid >> 1) : (wid >> 2);
    const int wn = (BN == 64) ? (wid & 1) : (wid & 3);
    const int m0 = blockIdx.y << 7;
    const int n0 = blockIdx.x * BN;
    const int a_row = lane & 15,  a_kb = lane & 16;
    const int b_row = ((lane >> 4) << 3) + (lane & 7), b_kb = ((lane >> 3) & 1) << 4;

    float acc[MT][4][4];
    #pragma unroll
    for (int i = 0; i < MT; i++)
        #pragma unroll
        for (int j = 0; j < 4; j++)
            #pragma unroll
            for (int t = 0; t < 4; t++) acc[i][j][t] = 0.0f;

    const int nch = K >> 5;
    #pragma unroll
    for (int s = 0; s < ST - 1; s++) {
        load_chunk<BN>(smb + s * BUFSZ, Ah, Al, Wh, Wl, m0, n0, K, s << 5, tid);
        CPC();
    }
    for (int c = 0; c < nch; c++) {
        if (ST == 3 && c + 1 < nch) CPW1(); else CPW0();
        __syncthreads();
        if (c + ST - 1 < nch) {
            load_chunk<BN>(smb + ((c + ST - 1) % ST) * BUFSZ, Ah, Al, Wh, Wl,
                           m0, n0, K, (c + ST - 1) << 5, tid);
            CPC();
        }
        const uint32_t ab = smb + (c % ST) * BUFSZ;
        const uint32_t wb = ab + 20480;
        #pragma unroll
        for (int ks = 0; ks < 2; ks++) {
            const int kbyte = ks * 32;
            uint32_t Bh[2][4], Bl[2][4];
            #pragma unroll
            for (int ng = 0; ng < 2; ng++) {
                const uint32_t roff = (wn*32 + ng*16 + b_row) * 80 + kbyte + b_kb;
                ldsm4(Bh[ng], wb + roff);
                ldsm4(Bl[ng], wb + BN * 80 + roff);
            }
            #pragma unroll
            for (int mt = 0; mt < MT; mt++) {
                uint32_t Af[4], Alf[4];
                const uint32_t aoff = (wm*(MT*16) + mt*16 + a_row) * 80 + kbyte + a_kb;
                ldsm4(Af,  ab + aoff);
                ldsm4(Alf, ab + 10240 + aoff);
                #pragma unroll
                for (int ng = 0; ng < 2; ng++)
                    #pragma unroll
                    for (int hf = 0; hf < 2; hf++) {
                        float* d = acc[mt][ng*2 + hf];
                        mma_bf16(d, Af,  Bh[ng] + hf*2);
                        mma_bf16(d, Alf, Bh[ng] + hf*2);
                        mma_bf16(d, Af,  Bl[ng] + hf*2);
                    }
            }
        }
    }

    // epilogue (per-CTA output select for fused QKV)
    __nv_bfloat16 *oh_ = Ch, *ol_ = Cl;
    int nst = N, nbase = n0;
    if (KH) {
        const int part = n0 >> 9;
        if (part == 1)      { oh_ = KH; ol_ = KL; }
        else if (part == 2) { oh_ = VH; ol_ = VL; }
        nbase = n0 & 511;
        nst = 512;
    }
    const int g = lane >> 2, tg = lane & 3;
    #pragma unroll
    for (int mt = 0; mt < MT; mt++) {
        #pragma unroll
        for (int nt = 0; nt < 4; nt++) {
            const int row  = m0 + wm*(MT*16) + mt*16 + g;
            const int colb = n0 + wn*32 + nt*8 + tg*2;      // bias index
            const int cols = nbase + wn*32 + nt*8 + tg*2;   // store index
            float b0 = bias ? bias[colb]     : 0.0f;
            float b1 = bias ? bias[colb + 1] : 0.0f;
            float v0 = acc[mt][nt][0] + b0, v1 = acc[mt][nt][1] + b1;
            float v2 = acc[mt][nt][2] + b0, v3 = acc[mt][nt][3] + b1;
            if (relu) {
                v0 = fmaxf(v0, 0.f); v1 = fmaxf(v1, 0.f);
                v2 = fmaxf(v2, 0.f); v3 = fmaxf(v3, 0.f);
            }
            const size_t o0 = (size_t)row * nst + cols;
            const size_t o1 = (size_t)(row + 8) * nst + cols;
            if (C) {
                *(float2*)&C[o0] = make_float2(v0, v1);
                *(float2*)&C[o1] = make_float2(v2, v3);
            }
            if (oh_) {
                *(uint32_t*)&oh_[o0] = pack_hi(v0, v1);
                *(uint32_t*)&oh_[o1] = pack_hi(v2, v3);
                *(uint32_t*)&ol_[o0] = pack_lo(v0, v1);
                *(uint32_t*)&ol_[o1] = pack_lo(v2, v3);
            }
        }
    }
}

// =====================================================================
// Tensor-core flash attention (causal): mma.sync bf16 hi/lo (R7).
// =====================================================================
#define AQS  0
#define AKS  36864
#define AVS  (36864 + 18432)
#define AAM  (36864 + 36864)
#define ASME (AAM + 256)

__global__ void __launch_bounds__(256) attn_tc(
    const __nv_bfloat16* __restrict__ Qh, const __nv_bfloat16* __restrict__ Ql,
    const __nv_bfloat16* __restrict__ Kh, const __nv_bfloat16* __restrict__ Kl,
    const __nv_bfloat16* __restrict__ Vh, const __nv_bfloat16* __restrict__ Vl,
    const int* __restrict__ amask,
    __nv_bfloat16* __restrict__ Oh, __nv_bfloat16* __restrict__ Ol)
{
    extern __shared__ char sm[];
    const uint32_t smb = smem_u32(sm);
    int* am_s = (int*)(sm + AAM);
    const int qt = blockIdx.x, bh = blockIdx.y;
    const int b = bh >> 3, h = bh & 7;
    const int tid = threadIdx.x, wid = tid >> 5, lane = tid & 31;
    const int g = lane >> 2, tg = lane & 3;
    const size_t base = (size_t)b * SEQ * D + h * 64;
    const int q0 = qt * 128;
    const int a_row = lane & 15, a_kb = lane & 16;
    const int b_row = ((lane >> 4) << 3) + (lane & 7), b_kb = ((lane >> 3) & 1) << 4;
    const int v_row = (((lane >> 3) & 1) << 3) + (lane & 7), v_byte = (lane >> 4) << 4;

    #pragma unroll
    for (int t = 0; t < 8; t++) {
        int s = tid + t * 256;
        int reg = s >> 10, row = (s >> 3) & 127, seg = s & 7;
        uint32_t dst = smb + AQS + reg * 18432 + row * 144 + seg * 16;
        const __nv_bfloat16* src = (reg ? Ql : Qh) + base + (size_t)(q0 + row) * D + seg * 8;
        CPA(dst, src);
    }
    CPC(); CPW0();
    __syncthreads();
    uint32_t qhf[4][4], qlf[4][4];
    #pragma unroll
    for (int ks = 0; ks < 4; ks++) {
        const uint32_t off = (wid*16 + a_row) * 144 + ks*32 + a_kb;
        ldsm4(qhf[ks], smb + AQS + off);
        ldsm4(qlf[ks], smb + AQS + 18432 + off);
    }

    float m_i[2] = {-1e30f, -1e30f}, l_i[2] = {0.f, 0.f};
    float o_acc[8][4];
    #pragma unroll
    for (int i = 0; i < 8; i++)
        #pragma unroll
        for (int j = 0; j < 4; j++) o_acc[i][j] = 0.f;

    const int row0 = q0 + wid*16 + g;
    const int ktmax = 2*qt + 1;
    for (int kt = 0; kt <= ktmax; kt++) {
        __syncthreads();
        #pragma unroll
        for (int t = 0; t < 4; t++) {
            int s = tid + t * 256;
            int reg = s >> 9, row = (s >> 3) & 63, seg = s & 7;
            uint32_t dst = smb + AKS + reg * 9216 + row * 144 + seg * 16;
            const __nv_bfloat16* src = (reg ? Kl : Kh) + base + (size_t)(kt*64 + row) * D + seg * 8;
            CPA(dst, src);
        }
        #pragma unroll
        for (int t = 0; t < 4; t++) {
            int s = tid + t * 256;
            int reg = s >> 9, row = (s >> 3) & 63, seg = s & 7;
            uint32_t dst = smb + AVS + reg * 9216 + row * 144 + seg * 16;
            const __nv_bfloat16* src = (reg ? Vl : Vh) + base + (size_t)(kt*64 + row) * D + seg * 8;
            CPA(dst, src);
        }
        CPC();
        if (tid < 64) am_s[tid] = amask[b * SEQ + kt*64 + tid];
        CPW0();
        __syncthreads();

        float sc[8][4];
        #pragma unroll
        for (int i = 0; i < 8; i++)
            #pragma unroll
            for (int j = 0; j < 4; j++) sc[i][j] = 0.f;
        #pragma unroll
        for (int ks = 0; ks < 4; ks++) {
            #pragma unroll
            for (int ng = 0; ng < 4; ng++) {
                uint32_t Bh[4], Bl[4];
                const uint32_t roff = (ng*16 + b_row) * 144 + ks*32 + b_kb;
                ldsm4(Bh, smb + AKS + roff);
                ldsm4(Bl, smb + AKS + 9216 + roff);
                #pragma unroll
                for (int hf = 0; hf < 2; hf++) {
                    float* d = sc[ng*2 + hf];
                    mma_bf16(d, qhf[ks], Bh + hf*2);
                    mma_bf16(d, qlf[ks], Bh + hf*2);
                    mma_bf16(d, qhf[ks], Bl + hf*2);
                }
            }
        }
        float mx0 = -1e30f, mx1 = -1e30f;
        #pragma unroll
        for (int nt = 0; nt < 8; nt++) {
            const int c0 = nt*8 + tg*2, c1 = c0 + 1;
            const int col0 = kt*64 + c0, col1 = col0 + 1;
            const int ok0 = am_s[c0], ok1 = am_s[c1];
            float s0 = sc[nt][0] * 0.125f, s1 = sc[nt][1] * 0.125f;
            float s2 = sc[nt][2] * 0.125f, s3 = sc[nt][3] * 0.125f;
            if (col0 > row0     || !ok0) s0 = -1e9f;
            if (col1 > row0     || !ok1) s1 = -1e9f;
            if (col0 > row0 + 8 || !ok0) s2 = -1e9f;
            if (col1 > row0 + 8 || !ok1) s3 = -1e9f;
            sc[nt][0] = s0; sc[nt][1] = s1; sc[nt][2] = s2; sc[nt][3] = s3;
            mx0 = fmaxf(mx0, fmaxf(s0, s1));
            mx1 = fmaxf(mx1, fmaxf(s2, s3));
        }
        mx0 = fmaxf(mx0, __shfl_xor_sync(0xffffffffu, mx0, 1));
        mx0 = fmaxf(mx0, __shfl_xor_sync(0xffffffffu, mx0, 2));
        mx1 = fmaxf(mx1, __shfl_xor_sync(0xffffffffu, mx1, 1));
        mx1 = fmaxf(mx1, __shfl_xor_sync(0xffffffffu, mx1, 2));
        const float mn0 = fmaxf(m_i[0], mx0), mn1 = fmaxf(m_i[1], mx1);
        const float al0 = fexp(m_i[0] - mn0), al1 = fexp(m_i[1] - mn1);
        float rs0 = 0.f, rs1 = 0.f;
        #pragma unroll
        for (int nt = 0; nt < 8; nt++) {
            float p0 = fexp(sc[nt][0] - mn0), p1 = fexp(sc[nt][1] - mn0);
            float p2 = fexp(sc[nt][2] - mn1), p3 = fexp(sc[nt][3] - mn1);
            sc[nt][0] = p0; sc[nt][1] = p1; sc[nt][2] = p2; sc[nt][3] = p3;
            rs0 += p0 + p1; rs1 += p2 + p3;
        }
        rs0 += __shfl_xor_sync(0xffffffffu, rs0, 1);
        rs0 += __shfl_xor_sync(0xffffffffu, rs0, 2);
        rs1 += __shfl_xor_sync(0xffffffffu, rs1, 1);
        rs1 += __shfl_xor_sync(0xffffffffu, rs1, 2);
        l_i[0] = l_i[0] * al0 + rs0;  m_i[0] = mn0;
        l_i[1] = l_i[1] * al1 + rs1;  m_i[1] = mn1;
        #pragma unroll
        for (int dt = 0; dt < 8; dt++) {
            o_acc[dt][0] *= al0; o_acc[dt][1] *= al0;
            o_acc[dt][2] *= al1; o_acc[dt][3] *= al1;
        }
        #pragma unroll
        for (int ks = 0; ks < 4; ks++) {
            uint32_t ph[4], pl[4];
            const int n0t = 2*ks, n1t = 2*ks + 1;
            ph[0] = pack_hi(sc[n0t][0], sc[n0t][1]); ph[1] = pack_hi(sc[n0t][2], sc[n0t][3]);
            ph[2] = pack_hi(sc[n1t][0], sc[n1t][1]); ph[3] = pack_hi(sc[n1t][2], sc[n1t][3]);
            pl[0] = pack_lo(sc[n0t][0], sc[n0t][1]); pl[1] = pack_lo(sc[n0t][2], sc[n0t][3]);
            pl[2] = pack_lo(sc[n1t][0], sc[n1t][1]); pl[3] = pack_lo(sc[n1t][2], sc[n1t][3]);
            #pragma unroll
            for (int dg = 0; dg < 4; dg++) {
                uint32_t Vhf[4], Vlf[4];
                const uint32_t voff = (ks*16 + v_row) * 144 + dg*32 + v_byte;
                ldsm4t(Vhf, smb + AVS + voff);
                ldsm4t(Vlf, smb + AVS + 9216 + voff);
                #pragma unroll
                for (int hf = 0; hf < 2; hf++) {
                    float* d = o_acc[dg*2 + hf];
                    mma_bf16(d, ph, Vhf + hf*2);
                    mma_bf16(d, pl, Vhf + hf*2);
                    mma_bf16(d, ph, Vlf + hf*2);
                }
            }
        }
    }
    const float inv0 = 1.0f / l_i[0], inv1 = 1.0f / l_i[1];
    #pragma unroll
    for (int dt = 0; dt < 8; dt++) {
        const int col = dt*8 + tg*2;
        const size_t o0 = base + (size_t)row0 * D + col;
        const size_t o1 = base + (size_t)(row0 + 8) * D + col;
        float v0 = o_acc[dt][0]*inv0, v1 = o_acc[dt][1]*inv0;
        float v2 = o_acc[dt][2]*inv1, v3 = o_acc[dt][3]*inv1;
        *(uint32_t*)&Oh[o0] = pack_hi(v0, v1);
        *(uint32_t*)&Oh[o1] = pack_hi(v2, v3);
        *(uint32_t*)&Ol[o0] = pack_lo(v0, v1);
        *(uint32_t*)&Ol[o1] = pack_lo(v2, v3);
    }
}

// ---------------- fused (residual add +) LayerNorm + bf16 split --------
__global__ void add_ln_kernel(float* __restrict__ X, const float* __restrict__ R,
                              const float* __restrict__ g, const float* __restrict__ b,
                              __nv_bfloat16* __restrict__ Xh,
                              __nv_bfloat16* __restrict__ Xl)
{
    const int row = blockIdx.x;
    __shared__ float sh[4];
    const int c = threadIdx.x * 4;
    float4 v = *(const float4*)&X[(size_t)row*D + c];
    if (R) {
        float4 r = *(const float4*)&R[(size_t)row*D + c];
        v.x += r.x; v.y += r.y; v.z += r.z; v.w += r.w;
    }
    float s = v.x + v.y + v.z + v.w;
    #pragma unroll
    for (int o = 16; o; o >>= 1) s += __shfl_xor_sync(0xffffffffu, s, o);
    if ((threadIdx.x & 31) == 0) sh[threadIdx.x >> 5] = s;
    __syncthreads();
    float mu = (sh[0] + sh[1] + sh[2] + sh[3]) * (1.0f / D);
    float dx = v.x - mu, dy = v.y - mu, dz = v.z - mu, dw = v.w - mu;
    float sq = dx*dx + dy*dy + dz*dz + dw*dw;
    #pragma unroll
    for (int o = 16; o; o >>= 1) sq += __shfl_xor_sync(0xffffffffu, sq, o);
    __syncthreads();
    if ((threadIdx.x & 31) == 0) sh[threadIdx.x >> 5] = sq;
    __syncthreads();
    float var = (sh[0] + sh[1] + sh[2] + sh[3]) * (1.0f / D);
    float inv = rsqrtf(var + 1e-5f);
    float4 gg = *(const float4*)&g[c];
    float4 bb = *(const float4*)&b[c];
    float o0 = dx*inv*gg.x + bb.x, o1 = dy*inv*gg.y + bb.y;
    float o2 = dz*inv*gg.z + bb.z, o3 = dw*inv*gg.w + bb.w;
    const size_t off = (size_t)row*D + c;
    *(float4*)&X[off] = make_float4(o0, o1, o2, o3);
    *(uint32_t*)&Xh[off]     = pack_hi(o0, o1);
    *(uint32_t*)&Xh[off + 2] = pack_hi(o2, o3);
    *(uint32_t*)&Xl[off]     = pack_lo(o0, o1);
    *(uint32_t*)&Xl[off + 2] = pack_lo(o2, o3);
}

// ---------------- host orchestration ----------------
extern "C" void kernel_launch(void* const* d_in, const int* in_sizes, int n_in,
                              void* d_out, int out_size)
{
    const int*   ids  = (const int*)  d_in[0];
    const int*   am   = (const int*)  d_in[1];
    const float* emb  = (const float*)d_in[2];
    const float* wq   = (const float*)d_in[3];  const float* bq = (const float*)d_in[4];
    const float* wk   = (const float*)d_in[5];  const float* bk = (const float*)d_in[6];
    const float* wv   = (const float*)d_in[7];  const float* bv = (const float*)d_in[8];
    const float* wo   = (const float*)d_in[9];  const float* bo = (const float*)d_in[10];
    const float* ln1g = (const float*)d_in[11]; const float* ln1b = (const float*)d_in[12];
    const float* w1   = (const float*)d_in[13]; const float* b1 = (const float*)d_in[14];
    const float* w2   = (const float*)d_in[15]; const float* b2 = (const float*)d_in[16];
    const float* ln2g = (const float*)d_in[17]; const float* ln2b = (const float*)d_in[18];
    const float* lnfg = (const float*)d_in[19]; const float* lnfb = (const float*)d_in[20];
    const float* lmw  = (const float*)d_in[21];
    float* out = (float*)d_out;

    static float *xp = nullptr, *tp, *bcat;
    static __nv_bfloat16 *xh, *xl, *qh, *ql, *kh, *kl, *vh, *vl, *oh, *ol, *fh, *fl, *wh, *wl;
    if (!xp) {
        cudaGetSymbolAddress((void**)&xp, g_x);
        cudaGetSymbolAddress((void**)&tp, g_t);
        cudaGetSymbolAddress((void**)&bcat, g_bcat);
        cudaGetSymbolAddress((void**)&xh, g_xh);
        cudaGetSymbolAddress((void**)&xl, g_xl);
        cudaGetSymbolAddress((void**)&qh, g_qh);
        cudaGetSymbolAddress((void**)&ql, g_ql);
        cudaGetSymbolAddress((void**)&kh, g_kh);
        cudaGetSymbolAddress((void**)&kl, g_kl);
        cudaGetSymbolAddress((void**)&vh, g_vh);
        cudaGetSymbolAddress((void**)&vl, g_vl);
        cudaGetSymbolAddress((void**)&oh, g_oh);
        cudaGetSymbolAddress((void**)&ol, g_ol);
        cudaGetSymbolAddress((void**)&fh, g_fh);
        cudaGetSymbolAddress((void**)&fl, g_fl);
        cudaGetSymbolAddress((void**)&wh, g_wh);
        cudaGetSymbolAddress((void**)&wl, g_wl);
        cudaFuncSetAttribute(attn_tc, cudaFuncAttributeMaxDynamicSharedMemorySize, ASME);
        cudaFuncSetAttribute(gemm_bf<64>,  cudaFuncAttributeMaxDynamicSharedMemorySize, 92160);
        cudaFuncSetAttribute(gemm_bf<128>, cudaFuncAttributeMaxDynamicSharedMemorySize, 81920);
    }

    // weight conversion (qkv interleaved per layer: [wq_l; wk_l; wv_l])
    conv_w<<<(6*DD)/1024,    256>>>(wq,  wh + OFF_QKV, wl + OFF_QKV, 6*DD, DD, 3*DD, 0);
    conv_w<<<(6*DD)/1024,    256>>>(wk,  wh + OFF_QKV, wl + OFF_QKV, 6*DD, DD, 3*DD, DD);
    conv_w<<<(6*DD)/1024,    256>>>(wv,  wh + OFF_QKV, wl + OFF_QKV, 6*DD, DD, 3*DD, 2*DD);
    conv_w<<<(6*DD)/1024,    256>>>(wo,  wh + OFF_WO,  wl + OFF_WO,  6*DD, 6*DD, 0, 0);
    conv_w<<<(6*FFD*D)/1024, 256>>>(w1,  wh + OFF_W1,  wl + OFF_W1,  6*FFD*D, 6*FFD*D, 0, 0);
    conv_w<<<(6*D*FFD)/1024, 256>>>(w2,  wh + OFF_W2,  wl + OFF_W2,  6*D*FFD, 6*D*FFD, 0, 0);
    conv_w<<<(VOC*D)/1024,   256>>>(lmw, wh + OFF_LM,  wl + OFF_LM,  VOC*D, VOC*D, 0, 0);
    bcat_kernel<<<(NL*3*D + 255)/256, 256>>>(bq, bk, bv);

    detect_ids_kernel<<<1, 256>>>(ids);
    embed_kernel<<<TOK, 128>>>(ids, emb);

    const dim3 gQKV(1536/64, TOK/128);  // (24, 32)
    const dim3 gD(D/64,  TOK/128);      // (8, 32)
    const dim3 gF(FFD/128, TOK/128);    // (16, 32)
    for (int l = 0; l < NL; l++) {
        gemm_bf<64><<<gQKV, 256, 92160>>>(xh, xl,
            wh + OFF_QKV + (size_t)l*3*DD, wl + OFF_QKV + (size_t)l*3*DD,
            bcat + l*1536, nullptr, qh, ql, kh, kl, vh, vl, TOK, 1536, D, 0);
        attn_tc<<<dim3(SEQ/128, BB*NH), 256, ASME>>>(qh, ql, kh, kl, vh, vl, am, oh, ol);
        gemm_bf<64><<<gD, 256, 92160>>>(oh, ol,
            wh + OFF_WO + (size_t)l*DD, wl + OFF_WO + (size_t)l*DD,
            bo + l*D, tp, nullptr, nullptr, nullptr, nullptr, nullptr, nullptr,
            TOK, D, D, 0);
        add_ln_kernel<<<TOK, 128>>>(xp, tp, ln1g + l*D, ln1b + l*D, xh, xl);
        gemm_bf<128><<<gF, 256, 81920>>>(xh, xl,
            wh + OFF_W1 + (size_t)l*FFD*D, wl + OFF_W1 + (size_t)l*FFD*D,
            b1 + l*FFD, nullptr, fh, fl, nullptr, nullptr, nullptr, nullptr,
            TOK, FFD, D, 1);
        gemm_bf<64><<<gD, 256, 92160>>>(fh, fl,
            wh + OFF_W2 + (size_t)l*D*FFD, wl + OFF_W2 + (size_t)l*D*FFD,
            b2 + l*D, tp, nullptr, nullptr, nullptr, nullptr, nullptr, nullptr,
            TOK, D, FFD, 0);
        add_ln_kernel<<<TOK, 128>>>(xp, tp, ln2g + l*D, ln2b + l*D, xh, xl);
    }
    add_ln_kernel<<<TOK, 128>>>(xp, nullptr, lnfg, lnfb, xh, xl);
    gemm_bf<64><<<gD, 256, 92160>>>(xh, xl, wh + OFF_LM, wl + OFF_LM,
        nullptr, out, nullptr, nullptr, nullptr, nullptr, nullptr, nullptr,
        TOK, VOC, D, 0);
}

// round 9
// speedup vs baseline: 1.0657x; 1.0657x over previous
#include <cuda_runtime.h>
#include <cuda_bf16.h>
#include <cstdint>

#define D   512
#define SEQ 1024
#define BB  4
#define NH  8
#define NL  6
#define FFD 2048
#define VOC 512
#define TOK (BB*SEQ)   // 4096
#define DD  (D*D)

// weight scratch offsets (element counts into g_wh/g_wl)
#define OFF_QKV 0                          // per layer: [wq; wk; wv] = 3*DD
#define OFF_WO  (18*DD)
#define OFF_W1  (24*DD)
#define OFF_W2  (OFF_W1 + 6*FFD*D)
#define OFF_LM  (OFF_W2 + 6*D*FFD)
#define W_TOTAL (OFF_LM + VOC*D)

// ---------------- device scratch (no allocations allowed) ----------------
__device__ float g_x[TOK*D];               // residual stream (fp32)
__device__ float g_t[TOK*D];               // gemm temp (fp32)
__device__ float g_bcat[NL*3*D];           // concat qkv bias
__device__ __nv_bfloat16 g_xh[TOK*D],  g_xl[TOK*D];    // residual hi/lo
__device__ __nv_bfloat16 g_qh[TOK*D],  g_ql[TOK*D];    // Q hi/lo
__device__ __nv_bfloat16 g_kh[TOK*D],  g_kl[TOK*D];    // K hi/lo
__device__ __nv_bfloat16 g_vh[TOK*D],  g_vl[TOK*D];    // V hi/lo
__device__ __nv_bfloat16 g_oh[TOK*D],  g_ol[TOK*D];    // attn out hi/lo
__device__ __nv_bfloat16 g_fh[TOK*FFD], g_fl[TOK*FFD]; // ffn hidden hi/lo
__device__ __nv_bfloat16 g_wh[W_TOTAL], g_wl[W_TOTAL]; // weights hi/lo
__device__ int g_idmode;

// ---------------- helpers ----------------
__device__ __forceinline__ uint32_t smem_u32(const void* p) {
    uint32_t a;
    asm("{ .reg .u64 t; cvta.to.shared.u64 t, %1; cvt.u32.u64 %0, t; }"
        : "=r"(a) : "l"(p));
    return a;
}
__device__ __forceinline__ void ldsm4(uint32_t* r, uint32_t addr) {
    asm volatile("ldmatrix.sync.aligned.m8n8.x4.shared.b16 {%0,%1,%2,%3}, [%4];"
                 : "=r"(r[0]), "=r"(r[1]), "=r"(r[2]), "=r"(r[3]) : "r"(addr));
}
__device__ __forceinline__ void ldsm4t(uint32_t* r, uint32_t addr) {
    asm volatile("ldmatrix.sync.aligned.m8n8.x4.trans.shared.b16 {%0,%1,%2,%3}, [%4];"
                 : "=r"(r[0]), "=r"(r[1]), "=r"(r[2]), "=r"(r[3]) : "r"(addr));
}
__device__ __forceinline__ void mma_bf16(float* d, const uint32_t* a,
                                         const uint32_t* b) {
    asm volatile("mma.sync.aligned.m16n8k16.row.col.f32.bf16.bf16.f32 "
                 "{%0,%1,%2,%3}, {%4,%5,%6,%7}, {%8,%9}, {%0,%1,%2,%3};"
                 : "+f"(d[0]), "+f"(d[1]), "+f"(d[2]), "+f"(d[3])
                 : "r"(a[0]), "r"(a[1]), "r"(a[2]), "r"(a[3]),
                   "r"(b[0]), "r"(b[1]));
}
#define CPA(dst, src) \
    asm volatile("cp.async.ca.shared.global [%0], [%1], 16;" :: "r"(dst), "l"(src))
#define CPC()  asm volatile("cp.async.commit_group;" ::: "memory")
#define CPW1() asm volatile("cp.async.wait_group 1;" ::: "memory")
#define CPW0() asm volatile("cp.async.wait_group 0;" ::: "memory")

__device__ __forceinline__ uint32_t pack_hi(float a, float b) {
    return (uint32_t)__bfloat16_as_ushort(__float2bfloat16(a)) |
           ((uint32_t)__bfloat16_as_ushort(__float2bfloat16(b)) << 16);
}
__device__ __forceinline__ uint32_t pack_lo(float a, float b) {
    float ra = a - __bfloat162float(__float2bfloat16(a));
    float rb = b - __bfloat162float(__float2bfloat16(b));
    return (uint32_t)__bfloat16_as_ushort(__float2bfloat16(ra)) |
           ((uint32_t)__bfloat16_as_ushort(__float2bfloat16(rb)) << 16);
}
// fast exp: 2^(x*log2e) via 5-FMA poly + exponent bit-stuff (no MUFU)
__device__ __forceinline__ float fexp(float x) {
    x = fmaxf(x, -80.0f);
    float t = x * 1.4426950408889634f;
    float fi = rintf(t);
    float f = t - fi;
    float p =              1.3333558146e-3f;
    p = fmaf(p, f, 9.6180209764e-3f);
    p = fmaf(p, f, 5.5504108664e-2f);
    p = fmaf(p, f, 2.4022650695e-1f);
    p = fmaf(p, f, 6.9314718056e-1f);
    p = fmaf(p, f, 1.0f);
    return __int_as_float(((int)fi + 127) << 23) * p;
}

// ---- single fused weight conversion: all 7 tensors, one launch ----------
__global__ void conv_all(const float* __restrict__ wq, const float* __restrict__ wk,
                         const float* __restrict__ wv, const float* __restrict__ wo,
                         const float* __restrict__ w1, const float* __restrict__ w2,
                         const float* __restrict__ lmw)
{
    long i = ((long)blockIdx.x * 256 + threadIdx.x) * 4;
    const float* src;
    size_t d;
    if (i < 6L*DD) {                      // wq -> interleaved qkv slot 0
        long j = i;  long l = j / DD, r = j - l * DD;
        src = wq + j;  d = (size_t)l * 3 * DD + r;
    } else if (i < 12L*DD) {              // wk -> slot 1
        long j = i - 6L*DD;  long l = j / DD, r = j - l * DD;
        src = wk + j;  d = (size_t)l * 3 * DD + DD + r;
    } else if (i < 18L*DD) {              // wv -> slot 2
        long j = i - 12L*DD;  long l = j / DD, r = j - l * DD;
        src = wv + j;  d = (size_t)l * 3 * DD + 2 * DD + r;
    } else if (i < 24L*DD) {              // wo
        long j = i - 18L*DD;  src = wo + j;  d = OFF_WO + j;
    } else if (i < 24L*DD + 6L*FFD*D) {   // w1
        long j = i - 24L*DD;  src = w1 + j;  d = OFF_W1 + j;
    } else if (i < 24L*DD + 12L*FFD*D) {  // w2
        long j = i - (24L*DD + 6L*FFD*D);  src = w2 + j;  d = OFF_W2 + j;
    } else {                              // lm
        long j = i - (24L*DD + 12L*FFD*D);  src = lmw + j;  d = OFF_LM + j;
    }
    float4 v = *(const float4*)src;
    *(uint32_t*)&g_wh[d]     = pack_hi(v.x, v.y);
    *(uint32_t*)&g_wh[d + 2] = pack_hi(v.z, v.w);
    *(uint32_t*)&g_wl[d]     = pack_lo(v.x, v.y);
    *(uint32_t*)&g_wl[d + 2] = pack_lo(v.z, v.w);
}

// concat qkv biases into g_bcat[l][1536]
__global__ void bcat_kernel(const float* __restrict__ bq,
                            const float* __restrict__ bk,
                            const float* __restrict__ bv)
{
    int i = blockIdx.x * 256 + threadIdx.x;
    if (i >= NL * 3 * D) return;
    int l = i / (3 * D), r = i % (3 * D);
    int part = r >> 9, d = r & 511;
    const float* s = part == 0 ? bq : part == 1 ? bk : bv;
    g_bcat[i] = s[l * D + d];
}

// ---------------- input_ids dtype detection ----------------
__global__ void detect_ids_kernel(const int* __restrict__ p) {
    __shared__ int any;
    if (threadIdx.x == 0) any = 0;
    __syncthreads();
    int loc = 0;
    for (int i = threadIdx.x; i < 2048; i += blockDim.x) loc |= p[2*i + 1];
    if (loc) atomicOr(&any, 1);
    __syncthreads();
    if (threadIdx.x == 0) g_idmode = any ? 1 : 0;
}

// ---------------- embedding + positional encoding (fp32 + hi/lo) -------
__global__ void embed_kernel(const int* __restrict__ ids,
                             const float* __restrict__ emb) {
    int bs = blockIdx.x;
    int s  = bs & (SEQ - 1);
    int id = g_idmode ? ids[bs] : ids[2*bs];
    const float* e = emb + (size_t)id * D;
    const float c = -9.210340371976184f / 512.0f;
    const int d0 = threadIdx.x * 4;
    float v[4];
    #pragma unroll
    for (int j = 0; j < 4; j++) {
        int d = d0 + j;
        float ang = (float)s * expf(c * (float)(d & ~1));
        float pe  = (d & 1) ? cosf(ang) : sinf(ang);
        v[j] = e[d] * 22.627416997969522f + pe;
    }
    const size_t off = (size_t)bs * D + d0;
    *(float4*)&g_x[off] = make_float4(v[0], v[1], v[2], v[3]);
    *(uint32_t*)&g_xh[off]     = pack_hi(v[0], v[1]);
    *(uint32_t*)&g_xh[off + 2] = pack_hi(v[2], v[3]);
    *(uint32_t*)&g_xl[off]     = pack_lo(v[0], v[1]);
    *(uint32_t*)&g_xl[off + 2] = pack_lo(v[2], v[3]);
}

// =====================================================================
// bf16 tensor-core GEMM, BN=128 (traffic-optimal), 2-stage cp.async.
// C = A @ W^T (+bias, opt ReLU). 3-term hi/lo split, fp32 acc.
// QKV mode: KH!=null -> N=1536 logical, per-CTA output select, stride 512.
// =====================================================================
__device__ __forceinline__ void load_chunk128(
    uint32_t sbuf,
    const __nv_bfloat16* __restrict__ Ah, const __nv_bfloat16* __restrict__ Al,
    const __nv_bfloat16* __restrict__ Wh, const __nv_bfloat16* __restrict__ Wl,
    int m0, int n0, int K, int kc, int tid)
{
    #pragma unroll
    for (int t = 0; t < 4; t++) {
        int s = tid + t * 256;
        int reg = s >> 9;
        int row = (s >> 2) & 127;
        int seg = s & 3;
        uint32_t dst = sbuf + reg * 10240 + row * 80 + seg * 16;
        const __nv_bfloat16* src = (reg ? Al : Ah) + (size_t)(m0 + row) * K + kc + seg * 8;
        CPA(dst, src);
    }
    #pragma unroll
    for (int t = 0; t < 4; t++) {
        int s = tid + t * 256;
        int reg = s >> 9;
        int row = (s >> 2) & 127;
        int seg = s & 3;
        uint32_t dst = sbuf + 20480 + reg * 10240 + row * 80 + seg * 16;
        const __nv_bfloat16* src = (reg ? Wl : Wh) + (size_t)(n0 + row) * K + kc + seg * 8;
        CPA(dst, src);
    }
}

__global__ void __launch_bounds__(256, 2) gemm_bf(
    const __nv_bfloat16* __restrict__ Ah, const __nv_bfloat16* __restrict__ Al,
    const __nv_bfloat16* __restrict__ Wh, const __nv_bfloat16* __restrict__ Wl,
    const float* __restrict__ bias, float* __restrict__ C,
    __nv_bfloat16* __restrict__ Ch, __nv_bfloat16* __restrict__ Cl,
    __nv_bfloat16* __restrict__ KH, __nv_bfloat16* __restrict__ KL,
    __nv_bfloat16* __restrict__ VH, __nv_bfloat16* __restrict__ VL,
    int M, int N, int K, int relu)
{
    extern __shared__ char sm[];
    const uint32_t smb = smem_u32(sm);
    constexpr int BUFSZ = 40960;
    const int tid = threadIdx.x, wid = tid >> 5, lane = tid & 31;
    const int wm = wid >> 2;          // 0..1 -> m offset 64*wm
    const int wn = wid & 3;           // 0..3 -> n offset 32*wn
    const int m0 = blockIdx.y << 7;
    const int n0 = blockIdx.x << 7;
    const int a_row = lane & 15,  a_kb = lane & 16;
    const int b_row = ((lane >> 4) << 3) + (lane & 7), b_kb = ((lane >> 3) & 1) << 4;

    float acc[4][4][4];
    #pragma unroll
    for (int i = 0; i < 4; i++)
        #pragma unroll
        for (int j = 0; j < 4; j++)
            #pragma unroll
            for (int t = 0; t < 4; t++) acc[i][j][t] = 0.0f;

    const int nch = K >> 5;
    load_chunk128(smb, Ah, Al, Wh, Wl, m0, n0, K, 0, tid);
    CPC();
    for (int c = 0; c < nch; c++) {
        CPW0();
        __syncthreads();
        if (c + 1 < nch) {
            load_chunk128(smb + ((c + 1) & 1) * BUFSZ, Ah, Al, Wh, Wl,
                          m0, n0, K, (c + 1) << 5, tid);
            CPC();
        }
        const uint32_t ab = smb + (c & 1) * BUFSZ;
        const uint32_t wb = ab + 20480;
        #pragma unroll
        for (int ks = 0; ks < 2; ks++) {
            const int kbyte = ks * 32;
            uint32_t Bh[2][4], Bl[2][4];
            #pragma unroll
            for (int ng = 0; ng < 2; ng++) {
                const uint32_t roff = (wn*32 + ng*16 + b_row) * 80 + kbyte + b_kb;
                ldsm4(Bh[ng], wb + roff);
                ldsm4(Bl[ng], wb + 10240 + roff);
            }
            #pragma unroll
            for (int mt = 0; mt < 4; mt++) {
                uint32_t Af[4], Alf[4];
                const uint32_t aoff = (wm*64 + mt*16 + a_row) * 80 + kbyte + a_kb;
                ldsm4(Af,  ab + aoff);
                ldsm4(Alf, ab + 10240 + aoff);
                #pragma unroll
                for (int ng = 0; ng < 2; ng++)
                    #pragma unroll
                    for (int hf = 0; hf < 2; hf++) {
                        float* d = acc[mt][ng*2 + hf];
                        mma_bf16(d, Af,  Bh[ng] + hf*2);
                        mma_bf16(d, Alf, Bh[ng] + hf*2);
                        mma_bf16(d, Af,  Bl[ng] + hf*2);
                    }
            }
        }
        __syncthreads();
    }

    // epilogue (per-CTA output select for fused QKV)
    __nv_bfloat16 *oh_ = Ch, *ol_ = Cl;
    int nst = N, nbase = n0;
    if (KH) {
        const int part = n0 >> 9;
        if (part == 1)      { oh_ = KH; ol_ = KL; }
        else if (part == 2) { oh_ = VH; ol_ = VL; }
        nbase = n0 & 511;
        nst = 512;
    }
    const int g = lane >> 2, tg = lane & 3;
    #pragma unroll
    for (int mt = 0; mt < 4; mt++) {
        #pragma unroll
        for (int nt = 0; nt < 4; nt++) {
            const int row  = m0 + wm*64 + mt*16 + g;
            const int colb = n0 + wn*32 + nt*8 + tg*2;      // bias index
            const int cols = nbase + wn*32 + nt*8 + tg*2;   // store index
            float b0 = bias ? bias[colb]     : 0.0f;
            float b1 = bias ? bias[colb + 1] : 0.0f;
            float v0 = acc[mt][nt][0] + b0, v1 = acc[mt][nt][1] + b1;
            float v2 = acc[mt][nt][2] + b0, v3 = acc[mt][nt][3] + b1;
            if (relu) {
                v0 = fmaxf(v0, 0.f); v1 = fmaxf(v1, 0.f);
                v2 = fmaxf(v2, 0.f); v3 = fmaxf(v3, 0.f);
            }
            const size_t o0 = (size_t)row * nst + cols;
            const size_t o1 = (size_t)(row + 8) * nst + cols;
            if (C) {
                *(float2*)&C[o0] = make_float2(v0, v1);
                *(float2*)&C[o1] = make_float2(v2, v3);
            }
            if (oh_) {
                *(uint32_t*)&oh_[o0] = pack_hi(v0, v1);
                *(uint32_t*)&oh_[o1] = pack_hi(v2, v3);
                *(uint32_t*)&ol_[o0] = pack_lo(v0, v1);
                *(uint32_t*)&ol_[o1] = pack_lo(v2, v3);
            }
        }
    }
}

// =====================================================================
// Tensor-core flash attention (causal), double-buffered K/V pipeline.
// Q smem region is recycled as K/V buffer 1 once Q frags are in registers.
// smem: 2 x (K 2x9216 + V 2x9216) = 73728, + am 2x256 -> 74240 B.
// =====================================================================
#define KVB(i) ((i) * 36864)
#define AAM    73728
#define ASME   (AAM + 512)

__global__ void __launch_bounds__(256) attn_tc(
    const __nv_bfloat16* __restrict__ Qh, const __nv_bfloat16* __restrict__ Ql,
    const __nv_bfloat16* __restrict__ Kh, const __nv_bfloat16* __restrict__ Kl,
    const __nv_bfloat16* __restrict__ Vh, const __nv_bfloat16* __restrict__ Vl,
    const int* __restrict__ amask,
    __nv_bfloat16* __restrict__ Oh, __nv_bfloat16* __restrict__ Ol)
{
    extern __shared__ char sm[];
    const uint32_t smb = smem_u32(sm);
    int* am_s = (int*)(sm + AAM);              // [2][64]
    const int qt = blockIdx.x, bh = blockIdx.y;
    const int b = bh >> 3, h = bh & 7;
    const int tid = threadIdx.x, wid = tid >> 5, lane = tid & 31;
    const int g = lane >> 2, tg = lane & 3;
    const size_t base = (size_t)b * SEQ * D + h * 64;
    const int q0 = qt * 128;
    const int a_row = lane & 15, a_kb = lane & 16;
    const int b_row = ((lane >> 4) << 3) + (lane & 7), b_kb = ((lane >> 3) & 1) << 4;
    const int v_row = (((lane >> 3) & 1) << 3) + (lane & 7), v_byte = (lane >> 4) << 4;

    // ---- Q into buffer 1 region, then to register fragments ----
    #pragma unroll
    for (int t = 0; t < 8; t++) {
        int s = tid + t * 256;
        int reg = s >> 10, row = (s >> 3) & 127, seg = s & 7;
        uint32_t dst = smb + KVB(1) + reg * 18432 + row * 144 + seg * 16;
        const __nv_bfloat16* src = (reg ? Ql : Qh) + base + (size_t)(q0 + row) * D + seg * 8;
        CPA(dst, src);
    }
    CPC(); CPW0();
    __syncthreads();
    uint32_t qhf[4][4], qlf[4][4];
    #pragma unroll
    for (int ks = 0; ks < 4; ks++) {
        const uint32_t off = (wid*16 + a_row) * 144 + ks*32 + a_kb;
        ldsm4(qhf[ks], smb + KVB(1) + off);
        ldsm4(qlf[ks], smb + KVB(1) + 18432 + off);
    }

    float m_i[2] = {-1e30f, -1e30f}, l_i[2] = {0.f, 0.f};
    float o_acc[8][4];
    #pragma unroll
    for (int i = 0; i < 8; i++)
        #pragma unroll
        for (int j = 0; j < 4; j++) o_acc[i][j] = 0.f;

    const int row0 = q0 + wid*16 + g;
    const int ktmax = 2*qt + 1;

    // prologue: issue K/V load for kt=0 into buffer 0 (doesn't touch Q region)
    {
        const uint32_t kv = smb + KVB(0);
        #pragma unroll
        for (int t = 0; t < 4; t++) {
            int s = tid + t * 256;
            int reg = s >> 9, row = (s >> 3) & 63, seg = s & 7;
            CPA(kv + reg * 9216 + row * 144 + seg * 16,
                (reg ? Kl : Kh) + base + (size_t)row * D + seg * 8);
        }
        #pragma unroll
        for (int t = 0; t < 4; t++) {
            int s = tid + t * 256;
            int reg = s >> 9, row = (s >> 3) & 63, seg = s & 7;
            CPA(kv + 18432 + reg * 9216 + row * 144 + seg * 16,
                (reg ? Vl : Vh) + base + (size_t)row * D + seg * 8);
        }
        if (tid < 64) am_s[tid] = amask[b * SEQ + tid];
        CPC();
    }

    for (int kt = 0; kt <= ktmax; kt++) {
        CPW0();                 // K/V(kt) arrived (overlapped with compute kt-1)
        __syncthreads();        // all warps done with buffer (kt+1)&1's old data
        if (kt + 1 <= ktmax) {  // prefetch next tile into the other buffer
            const uint32_t kv = smb + KVB((kt + 1) & 1);
            const size_t kb = base + (size_t)((kt + 1) * 64) * D;
            #pragma unroll
            for (int t = 0; t < 4; t++) {
                int s = tid + t * 256;
                int reg = s >> 9, row = (s >> 3) & 63, seg = s & 7;
                CPA(kv + reg * 9216 + row * 144 + seg * 16,
                    (reg ? Kl : Kh) + kb + (size_t)row * D + seg * 8);
            }
            #pragma unroll
            for (int t = 0; t < 4; t++) {
                int s = tid + t * 256;
                int reg = s >> 9, row = (s >> 3) & 63, seg = s & 7;
                CPA(kv + 18432 + reg * 9216 + row * 144 + seg * 16,
                    (reg ? Vl : Vh) + kb + (size_t)row * D + seg * 8);
            }
            if (tid < 64) am_s[((kt + 1) & 1) * 64 + tid] = amask[b * SEQ + (kt + 1) * 64 + tid];
            CPC();
        }
        const uint32_t kbuf = smb + KVB(kt & 1);
        const uint32_t vbuf = kbuf + 18432;
        const int* am = am_s + (kt & 1) * 64;

        // ---- scores: S = Q K^T (hi/lo 3-term) ----
        float sc[8][4];
        #pragma unroll
        for (int i = 0; i < 8; i++)
            #pragma unroll
            for (int j = 0; j < 4; j++) sc[i][j] = 0.f;
        #pragma unroll
        for (int ks = 0; ks < 4; ks++) {
            #pragma unroll
            for (int ng = 0; ng < 4; ng++) {
                uint32_t Bh[4], Bl[4];
                const uint32_t roff = (ng*16 + b_row) * 144 + ks*32 + b_kb;
                ldsm4(Bh, kbuf + roff);
                ldsm4(Bl, kbuf + 9216 + roff);
                #pragma unroll
                for (int hf = 0; hf < 2; hf++) {
                    float* d = sc[ng*2 + hf];
                    mma_bf16(d, qhf[ks], Bh + hf*2);
                    mma_bf16(d, qlf[ks], Bh + hf*2);
                    mma_bf16(d, qhf[ks], Bl + hf*2);
                }
            }
        }
        // ---- mask + scale + online softmax ----
        float mx0 = -1e30f, mx1 = -1e30f;
        #pragma unroll
        for (int nt = 0; nt < 8; nt++) {
            const int c0 = nt*8 + tg*2, c1 = c0 + 1;
            const int col0 = kt*64 + c0, col1 = col0 + 1;
            const int ok0 = am[c0], ok1 = am[c1];
            float s0 = sc[nt][0] * 0.125f, s1 = sc[nt][1] * 0.125f;
            float s2 = sc[nt][2] * 0.125f, s3 = sc[nt][3] * 0.125f;
            if (col0 > row0     || !ok0) s0 = -1e9f;
            if (col1 > row0     || !ok1) s1 = -1e9f;
            if (col0 > row0 + 8 || !ok0) s2 = -1e9f;
            if (col1 > row0 + 8 || !ok1) s3 = -1e9f;
            sc[nt][0] = s0; sc[nt][1] = s1; sc[nt][2] = s2; sc[nt][3] = s3;
            mx0 = fmaxf(mx0, fmaxf(s0, s1));
            mx1 = fmaxf(mx1, fmaxf(s2, s3));
        }
        mx0 = fmaxf(mx0, __shfl_xor_sync(0xffffffffu, mx0, 1));
        mx0 = fmaxf(mx0, __shfl_xor_sync(0xffffffffu, mx0, 2));
        mx1 = fmaxf(mx1, __shfl_xor_sync(0xffffffffu, mx1, 1));
        mx1 = fmaxf(mx1, __shfl_xor_sync(0xffffffffu, mx1, 2));
        const float mn0 = fmaxf(m_i[0], mx0), mn1 = fmaxf(m_i[1], mx1);
        const float al0 = fexp(m_i[0] - mn0), al1 = fexp(m_i[1] - mn1);
        float rs0 = 0.f, rs1 = 0.f;
        #pragma unroll
        for (int nt = 0; nt < 8; nt++) {
            float p0 = fexp(sc[nt][0] - mn0), p1 = fexp(sc[nt][1] - mn0);
            float p2 = fexp(sc[nt][2] - mn1), p3 = fexp(sc[nt][3] - mn1);
            sc[nt][0] = p0; sc[nt][1] = p1; sc[nt][2] = p2; sc[nt][3] = p3;
            rs0 += p0 + p1; rs1 += p2 + p3;
        }
        rs0 += __shfl_xor_sync(0xffffffffu, rs0, 1);
        rs0 += __shfl_xor_sync(0xffffffffu, rs0, 2);
        rs1 += __shfl_xor_sync(0xffffffffu, rs1, 1);
        rs1 += __shfl_xor_sync(0xffffffffu, rs1, 2);
        l_i[0] = l_i[0] * al0 + rs0;  m_i[0] = mn0;
        l_i[1] = l_i[1] * al1 + rs1;  m_i[1] = mn1;
        #pragma unroll
        for (int dt = 0; dt < 8; dt++) {
            o_acc[dt][0] *= al0; o_acc[dt][1] *= al0;
            o_acc[dt][2] *= al1; o_acc[dt][3] *= al1;
        }
        // ---- PV: O += P V ----
        #pragma unroll
        for (int ks = 0; ks < 4; ks++) {
            uint32_t ph[4], pl[4];
            const int n0t = 2*ks, n1t = 2*ks + 1;
            ph[0] = pack_hi(sc[n0t][0], sc[n0t][1]); ph[1] = pack_hi(sc[n0t][2], sc[n0t][3]);
            ph[2] = pack_hi(sc[n1t][0], sc[n1t][1]); ph[3] = pack_hi(sc[n1t][2], sc[n1t][3]);
            pl[0] = pack_lo(sc[n0t][0], sc[n0t][1]); pl[1] = pack_lo(sc[n0t][2], sc[n0t][3]);
            pl[2] = pack_lo(sc[n1t][0], sc[n1t][1]); pl[3] = pack_lo(sc[n1t][2], sc[n1t][3]);
            #pragma unroll
            for (int dg = 0; dg < 4; dg++) {
                uint32_t Vhf[4], Vlf[4];
                const uint32_t voff = (ks*16 + v_row) * 144 + dg*32 + v_byte;
                ldsm4t(Vhf, vbuf + voff);
                ldsm4t(Vlf, vbuf + 9216 + voff);
                #pragma unroll
                for (int hf = 0; hf < 2; hf++) {
                    float* d = o_acc[dg*2 + hf];
                    mma_bf16(d, ph, Vhf + hf*2);
                    mma_bf16(d, pl, Vhf + hf*2);
                    mma_bf16(d, ph, Vlf + hf*2);
                }
            }
        }
    }
    const float inv0 = 1.0f / l_i[0], inv1 = 1.0f / l_i[1];
    #pragma unroll
    for (int dt = 0; dt < 8; dt++) {
        const int col = dt*8 + tg*2;
        const size_t o0 = base + (size_t)row0 * D + col;
        const size_t o1 = base + (size_t)(row0 + 8) * D + col;
        float v0 = o_acc[dt][0]*inv0, v1 = o_acc[dt][1]*inv0;
        float v2 = o_acc[dt][2]*inv1, v3 = o_acc[dt][3]*inv1;
        *(uint32_t*)&Oh[o0] = pack_hi(v0, v1);
        *(uint32_t*)&Oh[o1] = pack_hi(v2, v3);
        *(uint32_t*)&Ol[o0] = pack_lo(v0, v1);
        *(uint32_t*)&Ol[o1] = pack_lo(v2, v3);
    }
}

// ---------------- fused (residual add +) LayerNorm + bf16 split --------
__global__ void add_ln_kernel(float* __restrict__ X, const float* __restrict__ R,
                              const float* __restrict__ g, const float* __restrict__ b,
                              __nv_bfloat16* __restrict__ Xh,
                              __nv_bfloat16* __restrict__ Xl)
{
    const int row = blockIdx.x;
    __shared__ float sh[4];
    const int c = threadIdx.x * 4;
    float4 v = *(const float4*)&X[(size_t)row*D + c];
    if (R) {
        float4 r = *(const float4*)&R[(size_t)row*D + c];
        v.x += r.x; v.y += r.y; v.z += r.z; v.w += r.w;
    }
    float s = v.x + v.y + v.z + v.w;
    #pragma unroll
    for (int o = 16; o; o >>= 1) s += __shfl_xor_sync(0xffffffffu, s, o);
    if ((threadIdx.x & 31) == 0) sh[threadIdx.x >> 5] = s;
    __syncthreads();
    float mu = (sh[0] + sh[1] + sh[2] + sh[3]) * (1.0f / D);
    float dx = v.x - mu, dy = v.y - mu, dz = v.z - mu, dw = v.w - mu;
    float sq = dx*dx + dy*dy + dz*dz + dw*dw;
    #pragma unroll
    for (int o = 16; o; o >>= 1) sq += __shfl_xor_sync(0xffffffffu, sq, o);
    __syncthreads();
    if ((threadIdx.x & 31) == 0) sh[threadIdx.x >> 5] = sq;
    __syncthreads();
    float var = (sh[0] + sh[1] + sh[2] + sh[3]) * (1.0f / D);
    float inv = rsqrtf(var + 1e-5f);
    float4 gg = *(const float4*)&g[c];
    float4 bb = *(const float4*)&b[c];
    float o0 = dx*inv*gg.x + bb.x, o1 = dy*inv*gg.y + bb.y;
    float o2 = dz*inv*gg.z + bb.z, o3 = dw*inv*gg.w + bb.w;
    const size_t off = (size_t)row*D + c;
    *(float4*)&X[off] = make_float4(o0, o1, o2, o3);
    *(uint32_t*)&Xh[off]     = pack_hi(o0, o1);
    *(uint32_t*)&Xh[off + 2] = pack_hi(o2, o3);
    *(uint32_t*)&Xl[off]     = pack_lo(o0, o1);
    *(uint32_t*)&Xl[off + 2] = pack_lo(o2, o3);
}

// ---------------- host orchestration ----------------
extern "C" void kernel_launch(void* const* d_in, const int* in_sizes, int n_in,
                              void* d_out, int out_size)
{
    const int*   ids  = (const int*)  d_in[0];
    const int*   am   = (const int*)  d_in[1];
    const float* emb  = (const float*)d_in[2];
    const float* wq   = (const float*)d_in[3];  const float* bq = (const float*)d_in[4];
    const float* wk   = (const float*)d_in[5];  const float* bk = (const float*)d_in[6];
    const float* wv   = (const float*)d_in[7];  const float* bv = (const float*)d_in[8];
    const float* wo   = (const float*)d_in[9];  const float* bo = (const float*)d_in[10];
    const float* ln1g = (const float*)d_in[11]; const float* ln1b = (const float*)d_in[12];
    const float* w1   = (const float*)d_in[13]; const float* b1 = (const float*)d_in[14];
    const float* w2   = (const float*)d_in[15]; const float* b2 = (const float*)d_in[16];
    const float* ln2g = (const float*)d_in[17]; const float* ln2b = (const float*)d_in[18];
    const float* lnfg = (const float*)d_in[19]; const float* lnfb = (const float*)d_in[20];
    const float* lmw  = (const float*)d_in[21];
    float* out = (float*)d_out;

    static float *xp = nullptr, *tp, *bcat;
    static __nv_bfloat16 *xh, *xl, *qh, *ql, *kh, *kl, *vh, *vl, *oh, *ol, *fh, *fl, *wh, *wl;
    if (!xp) {
        cudaGetSymbolAddress((void**)&xp, g_x);
        cudaGetSymbolAddress((void**)&tp, g_t);
        cudaGetSymbolAddress((void**)&bcat, g_bcat);
        cudaGetSymbolAddress((void**)&xh, g_xh);
        cudaGetSymbolAddress((void**)&xl, g_xl);
        cudaGetSymbolAddress((void**)&qh, g_qh);
        cudaGetSymbolAddress((void**)&ql, g_ql);
        cudaGetSymbolAddress((void**)&kh, g_kh);
        cudaGetSymbolAddress((void**)&kl, g_kl);
        cudaGetSymbolAddress((void**)&vh, g_vh);
        cudaGetSymbolAddress((void**)&vl, g_vl);
        cudaGetSymbolAddress((void**)&oh, g_oh);
        cudaGetSymbolAddress((void**)&ol, g_ol);
        cudaGetSymbolAddress((void**)&fh, g_fh);
        cudaGetSymbolAddress((void**)&fl, g_fl);
        cudaGetSymbolAddress((void**)&wh, g_wh);
        cudaGetSymbolAddress((void**)&wl, g_wl);
        cudaFuncSetAttribute(attn_tc, cudaFuncAttributeMaxDynamicSharedMemorySize, ASME);
        cudaFuncSetAttribute(gemm_bf, cudaFuncAttributeMaxDynamicSharedMemorySize, 81920);
    }

    conv_all<<<W_TOTAL/1024, 256>>>(wq, wk, wv, wo, w1, w2, lmw);
    bcat_kernel<<<(NL*3*D + 255)/256, 256>>>(bq, bk, bv);
    detect_ids_kernel<<<1, 256>>>(ids);
    embed_kernel<<<TOK, 128>>>(ids, emb);

    const dim3 gQKV(1536/128, TOK/128); // (12, 32)
    const dim3 gD(D/128,  TOK/128);     // (4, 32)
    const dim3 gF(FFD/128, TOK/128);    // (16, 32)
    for (int l = 0; l < NL; l++) {
        gemm_bf<<<gQKV, 256, 81920>>>(xh, xl,
            wh + OFF_QKV + (size_t)l*3*DD, wl + OFF_QKV + (size_t)l*3*DD,
            bcat + l*1536, nullptr, qh, ql, kh, kl, vh, vl, TOK, 1536, D, 0);
        attn_tc<<<dim3(SEQ/128, BB*NH), 256, ASME>>>(qh, ql, kh, kl, vh, vl, am, oh, ol);
        gemm_bf<<<gD, 256, 81920>>>(oh, ol,
            wh + OFF_WO + (size_t)l*DD, wl + OFF_WO + (size_t)l*DD,
            bo + l*D, tp, nullptr, nullptr, nullptr, nullptr, nullptr, nullptr,
            TOK, D, D, 0);
        add_ln_kernel<<<TOK, 128>>>(xp, tp, ln1g + l*D, ln1b + l*D, xh, xl);
        gemm_bf<<<gF, 256, 81920>>>(xh, xl,
            wh + OFF_W1 + (size_t)l*FFD*D, wl + OFF_W1 + (size_t)l*FFD*D,
            b1 + l*FFD, nullptr, fh, fl, nullptr, nullptr, nullptr, nullptr,
            TOK, FFD, D, 1);
        gemm_bf<<<gD, 256, 81920>>>(fh, fl,
            wh + OFF_W2 + (size_t)l*D*FFD, wl + OFF_W2 + (size_t)l*D*FFD,
            b2 + l*D, tp, nullptr, nullptr, nullptr, nullptr, nullptr, nullptr,
            TOK, D, FFD, 0);
        add_ln_kernel<<<TOK, 128>>>(xp, tp, ln2g + l*D, ln2b + l*D, xh, xl);
    }
    add_ln_kernel<<<TOK, 128>>>(xp, nullptr, lnfg, lnfb, xh, xl);
    gemm_bf<<<gD, 256, 81920>>>(xh, xl, wh + OFF_LM, wl + OFF_LM,
        nullptr, out, nullptr, nullptr, nullptr, nullptr, nullptr, nullptr,
        TOK, VOC, D, 0);
}